// round 13
// baseline (speedup 1.0000x reference)
#include <cuda_runtime.h>
#include <cuda_fp16.h>
#include <cstdint>

#define NN 8192
#define FIN 512
#define FF 256
#define MB 64          // rows per CTA in gat kernel
#define KC 64          // K chunk

// ---------------- device scratch (allocation-free rule) ----------------
__device__ float  g_h[NN * FF];                  // fp32 h row-major
__device__ __half g_hT[(size_t)FF * NN];         // fp16 h, feature-major (B operand)
__device__ __half g_wt_hi[(size_t)FF * FIN];     // W^T hi fp16 [n][k]
__device__ float  g_s1[NN], g_s2[NN];
__device__ unsigned g_mxkey;                     // ordered-uint key of max(s2)

// ---------------- helpers ----------------
__device__ __forceinline__ uint32_t smem_u32(const void* p) {
    uint32_t a;
    asm("{ .reg .u64 t; cvta.to.shared.u64 t, %1; cvt.u32.u64 %0, t; }" : "=r"(a) : "l"(p));
    return a;
}
__device__ __forceinline__ __half2 u2h2(uint32_t u) {
    __half2 h; *reinterpret_cast<uint32_t*>(&h) = u; return h;
}
__device__ __forceinline__ uint32_t h22u(__half2 h) {
    return *reinterpret_cast<uint32_t*>(&h);
}
__device__ __forceinline__ unsigned f2key(float f) {
    unsigned b = __float_as_uint(f);
    return (b & 0x80000000u) ? ~b : (b ^ 0x80000000u);
}
__device__ __forceinline__ float key2f(unsigned k) {
    unsigned b = (k & 0x80000000u) ? (k ^ 0x80000000u) : ~k;
    return __uint_as_float(b);
}
#define CP16(dst, src) \
    asm volatile("cp.async.cg.shared.global [%0], [%1], 16;" :: "r"(dst), "l"(src) : "memory")
#define LDSM4(r, addr) \
    asm volatile("ldmatrix.sync.aligned.m8n8.x4.shared.b16 {%0,%1,%2,%3}, [%4];" \
        : "=r"((r)[0]), "=r"((r)[1]), "=r"((r)[2]), "=r"((r)[3]) : "r"(addr))
#define MMA16816(d, a, b0, b1) \
    asm volatile("mma.sync.aligned.m16n8k16.row.col.f32.f16.f16.f32 " \
        "{%0,%1,%2,%3},{%4,%5,%6,%7},{%8,%9},{%0,%1,%2,%3};" \
        : "+f"((d)[0]), "+f"((d)[1]), "+f"((d)[2]), "+f"((d)[3]) \
        : "r"((a)[0]), "r"((a)[1]), "r"((a)[2]), "r"((a)[3]), "r"(b0), "r"(b1))
#define STSV2(addr, v0, v1) \
    asm volatile("st.shared.v2.b32 [%0], {%1,%2};" :: "r"(addr), "r"(v0), "r"(v1) : "memory")

// ---------------- SMEM layouts ----------------
// gat_hmma
#define SM_BD 0                      // 32768 B : BD tables (8192 j x 4B, uint2 per j-pair)
#define SM_P 32768                   // 2 x 9216 B : P tile 64 rows x 144B pitch
#define SM_B 51200                   // 2 x 36864 B : B tile 256 rows x 144B pitch
#define SM_AC 124928                 // 512 B : A2/C2 per row (prologue only)
#define SM_ZS 124928                 // 256 B : Z per row (epilogue; reuses AC space)
#define GAT_SMEM 125440
// gemm_hmma
#define GM_AH 0                      // 9216 : A hi 64 x 144B
#define GM_AL 9216                   // 9216 : A lo
#define GM_BH 18432                  // 36864 : B hi 256 x 144B (reused as T in epilogue)
#define GEMM_SMEM 55296

// ---------------------------------------------------------------------------
// Kernel 0: W [512,256] fp32 -> W^T hi fp16 [256,512]; also reset g_mxkey.
// ---------------------------------------------------------------------------
__global__ __launch_bounds__(FIN) void wconv(const float* __restrict__ W) {
    const int n = blockIdx.x, k = threadIdx.x;
    if (n == 0 && k == 0) g_mxkey = 0u;   // below every encoded float
    g_wt_hi[(size_t)n * FIN + k] = __float2half_rn(W[k * FF + n]);
}

// ---------------------------------------------------------------------------
// Kernel 1: h = X @ W on HMMA, 2-product split (Xh*Wh + Xl*Wh).
// ---------------------------------------------------------------------------
__global__ __launch_bounds__(256, 1) void gemm_hmma(const float* __restrict__ X) {
    extern __shared__ char smem[];
    const uint32_t sb = smem_u32(smem);
    const int t = threadIdx.x;
    const int lane = t & 31, wid = t >> 5;
    const int midx = wid >> 2, nidx = wid & 3;
    const int i0 = blockIdx.x * 64;

    const int xr = t >> 2, xs = t & 3;
    const float* xptr = X + (size_t)(i0 + xr) * FIN + xs * 16;
    float4 xv[4];
#pragma unroll
    for (int q = 0; q < 4; q++) xv[q] = reinterpret_cast<const float4*>(xptr)[q];

    const __half* wh = g_wt_hi + (size_t)t * FIN;
    const uint32_t dBH = sb + GM_BH + (uint32_t)t * 144;
#pragma unroll
    for (int m = 0; m < 8; m++) CP16(dBH + m * 16, wh + m * 8);
    asm volatile("cp.async.commit_group;" ::: "memory");

    float acc[2][8][4];
#pragma unroll
    for (int a = 0; a < 2; a++)
#pragma unroll
        for (int b = 0; b < 8; b++)
#pragma unroll
            for (int c = 0; c < 4; c++) acc[a][b][c] = 0.f;

    const uint32_t arow = (uint32_t)(midx * 32 + ((lane >> 3) & 1) * 8 + (lane & 7));
    const uint32_t acolb = (uint32_t)((lane >> 4) * 16);
    const uint32_t brow0 = (uint32_t)(nidx * 64 + (lane >> 4) * 8 + (lane & 7));
    const uint32_t bcolb = (uint32_t)(((lane >> 3) & 1) * 16);

#pragma unroll 1
    for (int c = 0; c < 8; c++) {
        {
            const uint32_t aH = sb + GM_AH + (uint32_t)xr * 144 + (uint32_t)xs * 32;
            const uint32_t aL = sb + GM_AL + (uint32_t)xr * 144 + (uint32_t)xs * 32;
#pragma unroll
            for (int q = 0; q < 4; q++) {
                float4 v = xv[q];
                __half hx = __float2half_rn(v.x), hy = __float2half_rn(v.y);
                __half hz = __float2half_rn(v.z), hw = __float2half_rn(v.w);
                __half lx = __float2half_rn(v.x - __half2float(hx));
                __half ly = __float2half_rn(v.y - __half2float(hy));
                __half lz = __float2half_rn(v.z - __half2float(hz));
                __half lw = __float2half_rn(v.w - __half2float(hw));
                STSV2(aH + q * 8, h22u(__halves2half2(hx, hy)), h22u(__halves2half2(hz, hw)));
                STSV2(aL + q * 8, h22u(__halves2half2(lx, ly)), h22u(__halves2half2(lz, lw)));
            }
        }
        asm volatile("cp.async.wait_group 0;" ::: "memory");
        __syncthreads();
        if (c < 7) {
            const float* xp = xptr + (c + 1) * KC;
#pragma unroll
            for (int q = 0; q < 4; q++) xv[q] = reinterpret_cast<const float4*>(xp)[q];
        }
#pragma unroll
        for (int k16 = 0; k16 < 4; k16++) {
            uint32_t ah[2][4], al[2][4];
#pragma unroll
            for (int mt = 0; mt < 2; mt++) {
                LDSM4(ah[mt], sb + GM_AH + (arow + mt * 16) * 144 + k16 * 32 + acolb);
                LDSM4(al[mt], sb + GM_AL + (arow + mt * 16) * 144 + k16 * 32 + acolb);
            }
#pragma unroll
            for (int pr2 = 0; pr2 < 4; pr2++) {
                uint32_t bh[4];
                LDSM4(bh, sb + GM_BH + (brow0 + pr2 * 16) * 144 + k16 * 32 + bcolb);
#pragma unroll
                for (int mt = 0; mt < 2; mt++) {
                    MMA16816(acc[mt][2 * pr2], ah[mt], bh[0], bh[1]);
                    MMA16816(acc[mt][2 * pr2], al[mt], bh[0], bh[1]);
                    MMA16816(acc[mt][2 * pr2 + 1], ah[mt], bh[2], bh[3]);
                    MMA16816(acc[mt][2 * pr2 + 1], al[mt], bh[2], bh[3]);
                }
            }
        }
        __syncthreads();
        if (c < 7) {
#pragma unroll
            for (int m = 0; m < 8; m++) CP16(dBH + m * 16, wh + (c + 1) * KC + m * 8);
            asm volatile("cp.async.commit_group;" ::: "memory");
        }
    }

    // ---- epilogue: g_h fp32 + transpose to g_hT fp16 ----
#pragma unroll
    for (int mt = 0; mt < 2; mt++) {
        int lr0 = midx * 32 + mt * 16 + (lane >> 2);
        float* o0 = g_h + (size_t)(i0 + lr0) * FF;
#pragma unroll
        for (int nt = 0; nt < 8; nt++) {
            int col = nidx * 64 + nt * 8 + (lane & 3) * 2;
            *reinterpret_cast<float2*>(o0 + col) = make_float2(acc[mt][nt][0], acc[mt][nt][1]);
            *reinterpret_cast<float2*>(o0 + 8 * FF + col) = make_float2(acc[mt][nt][2], acc[mt][nt][3]);
            char* tb = smem + GM_BH + col * 144;
            *reinterpret_cast<__half*>(tb + lr0 * 2) = __float2half_rn(acc[mt][nt][0]);
            *reinterpret_cast<__half*>(tb + 144 + lr0 * 2) = __float2half_rn(acc[mt][nt][1]);
            *reinterpret_cast<__half*>(tb + (lr0 + 8) * 2) = __float2half_rn(acc[mt][nt][2]);
            *reinterpret_cast<__half*>(tb + 144 + (lr0 + 8) * 2) = __float2half_rn(acc[mt][nt][3]);
        }
    }
    __syncthreads();
    {
        uint4* dst = reinterpret_cast<uint4*>(g_hT + (size_t)t * NN + i0);
#pragma unroll
        for (int i = 0; i < 8; i++)
            dst[i] = *reinterpret_cast<const uint4*>(smem + GM_BH + t * 144 + i * 16);
    }
}

// ---------------------------------------------------------------------------
// Kernel 2: s1, s2 dot products (warp per row) + global max(s2) via atomicMax
// ---------------------------------------------------------------------------
__global__ __launch_bounds__(256) void svec_kernel(const float* __restrict__ a) {
    __shared__ float as[2 * FF];
    const int t = threadIdx.x;
    as[t] = a[t];
    as[t + 256] = a[t + 256];
    __syncthreads();
    const int warp = t >> 5, lane = t & 31;
    const int row = blockIdx.x * 8 + warp;
    float s1 = 0.f, s2 = 0.f;
#pragma unroll
    for (int q = 0; q < 8; q++) {
        int f = lane + 32 * q;
        float v = g_h[row * FF + f];
        s1 = fmaf(v, as[f], s1);
        s2 = fmaf(v, as[FF + f], s2);
    }
#pragma unroll
    for (int o = 16; o; o >>= 1) {
        s1 += __shfl_xor_sync(0xFFFFFFFFu, s1, o);
        s2 += __shfl_xor_sync(0xFFFFFFFFu, s2, o);
    }
    if (lane == 0) {
        g_s1[row] = s1;
        g_s2[row] = s2;
        atomicMax(&g_mxkey, f2key(s2));
    }
}

// ---------------------------------------------------------------------------
// P generator: 8 j's per thread (2 bd quads, 2 adj uint4), fp32 Z accum.
// ---------------------------------------------------------------------------
__device__ __forceinline__ void pgen8(uint32_t sb, const char* smem, int bufp, int jc,
                                      const uint4& I0, const uint4& I1,
                                      __half2 A2, __half2 C2, int pr_, int seg,
                                      float& z) {
    const uint4* bd4s = reinterpret_cast<const uint4*>(smem + SM_BD) + (jc >> 2) + seg * 2;
    const uint32_t pst = sb + SM_P + (uint32_t)bufp * 9216 + (uint32_t)pr_ * 144 + (uint32_t)seg * 16;
    uint32_t m0 = (uint32_t)I0.x * 0x3C00u + (uint32_t)I0.y * 0x3C000000u;
    uint32_t m1 = (uint32_t)I0.z * 0x3C00u + (uint32_t)I0.w * 0x3C000000u;
    uint32_t m2 = (uint32_t)I1.x * 0x3C00u + (uint32_t)I1.y * 0x3C000000u;
    uint32_t m3 = (uint32_t)I1.z * 0x3C00u + (uint32_t)I1.w * 0x3C000000u;
    uint4 bd0 = bd4s[0], bd1 = bd4s[1];
    __half2 a0 = __hmax2(__hmul2(A2, u2h2(bd0.x)), __hmul2(C2, u2h2(bd0.y)));
    __half2 a1 = __hmax2(__hmul2(A2, u2h2(bd0.z)), __hmul2(C2, u2h2(bd0.w)));
    __half2 a2 = __hmax2(__hmul2(A2, u2h2(bd1.x)), __hmul2(C2, u2h2(bd1.y)));
    __half2 a3 = __hmax2(__hmul2(A2, u2h2(bd1.z)), __hmul2(C2, u2h2(bd1.w)));
    __half2 r0 = __hmul2(a0, u2h2(m0));
    __half2 r1 = __hmul2(a1, u2h2(m1));
    __half2 r2 = __hmul2(a2, u2h2(m2));
    __half2 r3 = __hmul2(a3, u2h2(m3));
    STSV2(pst, h22u(r0), h22u(r1));
    STSV2(pst + 8, h22u(r2), h22u(r3));
    float2 f0 = __half22float2(r0), f1 = __half22float2(r1);
    float2 f2 = __half22float2(r2), f3 = __half22float2(r3);
    z += (f0.x + f0.y) + (f1.x + f1.y) + (f2.x + f2.y) + (f3.x + f3.y);
}

// ---------------------------------------------------------------------------
// Kernel 4: fused GAT on HMMA. 128 CTAs x (M=64, N=256), K=8192 in 64-chunks.
// 512 threads (16 warps, 4/SMSP), warp tile 32x32, fragment double-buffering
// across k16 steps. BD/AC tables in prologue; Z from pgen; 1 barrier/chunk.
// ---------------------------------------------------------------------------
__global__ __launch_bounds__(512, 1) void gat_hmma(const int* __restrict__ adj,
                                                   float* __restrict__ out) {
    extern __shared__ char smem[];
    const uint32_t sb = smem_u32(smem);
    const int t = threadIdx.x;
    const int lane = t & 31, wid = t >> 5;
    const int midx = wid >> 3, nidx = wid & 7;   // warp grid 2 x 8
    const int i0 = blockIdx.x * MB;

    const int pr_ = t >> 3;       // P-gen row 0..63
    const int seg = t & 7;        // 8 j's per thread
    const int* adjrow = adj + (size_t)(i0 + pr_) * NN + seg * 8;

    // B(0) cp.async: thread t copies half a hT row (64 B)
    const int brow = t >> 1, bhalf = t & 1;
    const __half* hrow = g_hT + (size_t)brow * NN + bhalf * 32;
    const uint32_t bdst = sb + SM_B + (uint32_t)brow * 144 + (uint32_t)bhalf * 64;
#pragma unroll
    for (int i = 0; i < 4; i++) CP16(bdst + i * 16, hrow + i * 8);
    asm volatile("cp.async.commit_group;" ::: "memory");

    // adj chunk 0 (latency overlaps table gen)
    uint4 I0 = reinterpret_cast<const uint4*>(adjrow)[0];
    uint4 I1 = reinterpret_cast<const uint4*>(adjrow)[1];

    // ---- build BD tables (8192 j) + AC (64 rows) in smem ----
    const float mx = key2f(g_mxkey);
    {
        const float2* s2p = reinterpret_cast<const float2*>(g_s2);
        uint2* bd = reinterpret_cast<uint2*>(smem + SM_BD);
        for (int j2 = t; j2 < NN / 2; j2 += 512) {
            float2 v = s2p[j2];
            float v0 = v.x - mx, v1 = v.y - mx;
            __half B0 = __float2half_rn(__expf(v0)), B1 = __float2half_rn(__expf(v1));
            __half D0 = __float2half_rn(__expf(0.2f * v0)), D1 = __float2half_rn(__expf(0.2f * v1));
            bd[j2] = make_uint2(h22u(__halves2half2(B0, B1)), h22u(__halves2half2(D0, D1)));
        }
        if (t < MB) {
            float u = g_s1[i0 + t] + mx;
            float mm = fmaxf(u, 0.2f * u);
            __half A = __float2half_rn(__expf(u - mm));
            __half C = __float2half_rn(__expf(0.2f * u - mm));
            reinterpret_cast<uint2*>(smem + SM_AC)[t] =
                make_uint2(h22u(__halves2half2(A, A)), h22u(__halves2half2(C, C)));
        }
    }
    __syncthreads();  // BD + AC visible
    const uint2 ac = reinterpret_cast<const uint2*>(smem + SM_AC)[pr_];
    const __half2 A2 = u2h2(ac.x);
    const __half2 C2 = u2h2(ac.y);

    float z = 0.f;
    pgen8(sb, smem, 0, 0, I0, I1, A2, C2, pr_, seg, z);  // P(0)
    {   // adj chunk 1
        const uint4* na = reinterpret_cast<const uint4*>(adjrow + KC);
        I0 = na[0]; I1 = na[1];
    }

    float acc[2][4][4];
#pragma unroll
    for (int a = 0; a < 2; a++)
#pragma unroll
        for (int b = 0; b < 4; b++)
#pragma unroll
            for (int c = 0; c < 4; c++) acc[a][b][c] = 0.f;

    const uint32_t arow = (uint32_t)(midx * 32 + ((lane >> 3) & 1) * 8 + (lane & 7));
    const uint32_t acolb = (uint32_t)((lane >> 4) * 16);
    const uint32_t brow0 = (uint32_t)(nidx * 32 + (lane >> 4) * 8 + (lane & 7));
    const uint32_t bcolb = (uint32_t)(((lane >> 3) & 1) * 16);

#pragma unroll 1
    for (int c = 0; c < 128; c++) {
        const int buf = c & 1;
        const int jc = c * KC;

        asm volatile("cp.async.wait_group 0;" ::: "memory");  // B(c) landed
        __syncthreads();                                      // P(c) + B(c) visible

        if (c < 127) {  // stage B(c+1)
            const __half* sH = hrow + jc + KC;
            const uint32_t dH = sb + SM_B + (uint32_t)(buf ^ 1) * 36864 +
                                (uint32_t)brow * 144 + (uint32_t)bhalf * 64;
#pragma unroll
            for (int i = 0; i < 4; i++) CP16(dH + i * 16, sH + i * 8);
            asm volatile("cp.async.commit_group;" ::: "memory");
        }

        const uint32_t Pb = sb + SM_P + (uint32_t)buf * 9216;
        const uint32_t Bb = sb + SM_B + (uint32_t)buf * 36864;

        // fragment pipeline: load k16=0 into pipe 0
        uint32_t af[2][2][4], bf[2][2][4];
        LDSM4(af[0][0], Pb + arow * 144 + acolb);
        LDSM4(af[0][1], Pb + (arow + 16) * 144 + acolb);
        LDSM4(bf[0][0], Bb + brow0 * 144 + bcolb);
        LDSM4(bf[0][1], Bb + (brow0 + 16) * 144 + bcolb);

#pragma unroll
        for (int k16 = 0; k16 < 4; k16++) {
            const int cur = k16 & 1, nxt = cur ^ 1;
            if (k16 < 3) {  // prefetch next k16 fragments under the MMAs
                const uint32_t ko = (uint32_t)(k16 + 1) * 32;
                LDSM4(af[nxt][0], Pb + arow * 144 + ko + acolb);
                LDSM4(af[nxt][1], Pb + (arow + 16) * 144 + ko + acolb);
                LDSM4(bf[nxt][0], Bb + brow0 * 144 + ko + bcolb);
                LDSM4(bf[nxt][1], Bb + (brow0 + 16) * 144 + ko + bcolb);
            }
#pragma unroll
            for (int mt = 0; mt < 2; mt++)
#pragma unroll
                for (int bt = 0; bt < 2; bt++) {
                    MMA16816(acc[mt][2 * bt], af[cur][mt], bf[cur][bt][0], bf[cur][bt][1]);
                    MMA16816(acc[mt][2 * bt + 1], af[cur][mt], bf[cur][bt][2], bf[cur][bt][3]);
                }
            if (k16 == 1) {  // P-gen(c+1) into other buffer (disjoint)
                if (c < 127)
                    pgen8(sb, smem, buf ^ 1, jc + KC, I0, I1, A2, C2, pr_, seg, z);
                if (c < 126) {  // adj chunk c+2
                    const uint4* na = reinterpret_cast<const uint4*>(adjrow + jc + 2 * KC);
                    I0 = na[0]; I1 = na[1];
                }
            }
        }
    }
    __syncthreads();

    // ---- Z: reduce over the 8 seg-threads of each row (same warp) ----
    z += __shfl_xor_sync(0xFFFFFFFFu, z, 1);
    z += __shfl_xor_sync(0xFFFFFFFFu, z, 2);
    z += __shfl_xor_sync(0xFFFFFFFFu, z, 4);
    float* zs = reinterpret_cast<float*>(smem + SM_ZS);
    if (seg == 0) zs[pr_] = z;
    __syncthreads();

    // ---- epilogue: 1/Z + ELU + store ----
#pragma unroll
    for (int mt = 0; mt < 2; mt++) {
        int lr0 = midx * 32 + mt * 16 + (lane >> 2);
        float inv0 = 1.0f / zs[lr0];
        float inv1 = 1.0f / zs[lr0 + 8];
        float* o0 = out + (size_t)(i0 + lr0) * FF;
#pragma unroll
        for (int nt = 0; nt < 4; nt++) {
            int col = nidx * 32 + nt * 8 + (lane & 3) * 2;
            float v0 = acc[mt][nt][0] * inv0, v1 = acc[mt][nt][1] * inv0;
            float v2 = acc[mt][nt][2] * inv1, v3 = acc[mt][nt][3] * inv1;
            v0 = v0 > 0.f ? v0 : (__expf(v0) - 1.f);
            v1 = v1 > 0.f ? v1 : (__expf(v1) - 1.f);
            v2 = v2 > 0.f ? v2 : (__expf(v2) - 1.f);
            v3 = v3 > 0.f ? v3 : (__expf(v3) - 1.f);
            *reinterpret_cast<float2*>(o0 + col) = make_float2(v0, v1);
            *reinterpret_cast<float2*>(o0 + 8 * FF + col) = make_float2(v2, v3);
        }
    }
}

// ---------------------------------------------------------------------------
extern "C" void kernel_launch(void* const* d_in, const int* in_sizes, int n_in,
                              void* d_out, int out_size) {
    const float* X = (const float*)d_in[0];   // [8192, 512]
    const int* adj = (const int*)d_in[1];     // [8192, 8192]
    const float* W = (const float*)d_in[2];   // [512, 256]
    const float* a = (const float*)d_in[3];   // [512, 1]
    float* out = (float*)d_out;               // [8192, 256]

    cudaFuncSetAttribute(gemm_hmma, cudaFuncAttributeMaxDynamicSharedMemorySize, GEMM_SMEM);
    cudaFuncSetAttribute(gat_hmma, cudaFuncAttributeMaxDynamicSharedMemorySize, GAT_SMEM);

    wconv<<<FF, FIN>>>(W);
    gemm_hmma<<<NN / 64, 256, GEMM_SMEM>>>(X);
    svec_kernel<<<NN / 8, 256>>>(a);
    gat_hmma<<<NN / MB, 512, GAT_SMEM>>>(adj, out);
}

// round 17
// speedup vs baseline: 1.2659x; 1.2659x over previous
#include <cuda_runtime.h>
#include <cuda_fp16.h>
#include <cstdint>

#define NN 8192
#define FIN 512
#define FF 256
#define MB 64          // rows per CTA in gat kernel
#define KC 64          // K chunk

// ---------------- device scratch (allocation-free rule) ----------------
__device__ float  g_h[NN * FF];                  // fp32 h row-major
__device__ __half g_hT[(size_t)FF * NN];         // fp16 h, feature-major (B operand)
__device__ __half g_wt_hi[(size_t)FF * FIN];     // W^T hi fp16 [n][k]
__device__ float  g_s1[NN], g_s2[NN];
__device__ unsigned g_mxkey;                     // ordered-uint key of max(s2)

// ---------------- helpers ----------------
__device__ __forceinline__ uint32_t smem_u32(const void* p) {
    uint32_t a;
    asm("{ .reg .u64 t; cvta.to.shared.u64 t, %1; cvt.u32.u64 %0, t; }" : "=r"(a) : "l"(p));
    return a;
}
__device__ __forceinline__ __half2 u2h2(uint32_t u) {
    __half2 h; *reinterpret_cast<uint32_t*>(&h) = u; return h;
}
__device__ __forceinline__ uint32_t h22u(__half2 h) {
    return *reinterpret_cast<uint32_t*>(&h);
}
__device__ __forceinline__ unsigned f2key(float f) {
    unsigned b = __float_as_uint(f);
    return (b & 0x80000000u) ? ~b : (b ^ 0x80000000u);
}
__device__ __forceinline__ float key2f(unsigned k) {
    unsigned b = (k & 0x80000000u) ? (k ^ 0x80000000u) : ~k;
    return __uint_as_float(b);
}
#define CP16(dst, src) \
    asm volatile("cp.async.cg.shared.global [%0], [%1], 16;" :: "r"(dst), "l"(src) : "memory")
#define LDSM4(r, addr) \
    asm volatile("ldmatrix.sync.aligned.m8n8.x4.shared.b16 {%0,%1,%2,%3}, [%4];" \
        : "=r"((r)[0]), "=r"((r)[1]), "=r"((r)[2]), "=r"((r)[3]) : "r"(addr))
#define MMA16816(d, a, b0, b1) \
    asm volatile("mma.sync.aligned.m16n8k16.row.col.f32.f16.f16.f32 " \
        "{%0,%1,%2,%3},{%4,%5,%6,%7},{%8,%9},{%0,%1,%2,%3};" \
        : "+f"((d)[0]), "+f"((d)[1]), "+f"((d)[2]), "+f"((d)[3]) \
        : "r"((a)[0]), "r"((a)[1]), "r"((a)[2]), "r"((a)[3]), "r"(b0), "r"(b1))
#define STSV2(addr, v0, v1) \
    asm volatile("st.shared.v2.b32 [%0], {%1,%2};" :: "r"(addr), "r"(v0), "r"(v1) : "memory")

// ---------------- SMEM layouts ----------------
// gat_hmma
#define SM_BD 0                      // 32768 B : BD tables (8192 j x 4B)
#define SM_P 32768                   // 2 x 9216 B : P tile 64 rows x 144B pitch
#define SM_B 51200                   // 2 x 36864 B : B tile 256 rows x 144B pitch
#define SM_AC 124928                 // 512 B : A2/C2 per row (prologue only)
#define SM_ZS 124928                 // 256 B : Z per row (epilogue; reuses AC space)
#define GAT_SMEM 125440
// gemm_hmma
#define GM_AH 0                      // 9216 : A hi 64 x 144B
#define GM_AL 9216                   // 9216 : A lo
#define GM_BH 18432                  // 36864 : B hi 256 x 144B (reused as T in epilogue)
#define GEMM_SMEM 55296

// ---------------------------------------------------------------------------
// Kernel 0: W [512,256] fp32 -> W^T hi fp16 [256,512]; also reset g_mxkey.
// ---------------------------------------------------------------------------
__global__ __launch_bounds__(FIN) void wconv(const float* __restrict__ W) {
    const int n = blockIdx.x, k = threadIdx.x;
    if (n == 0 && k == 0) g_mxkey = 0u;
    g_wt_hi[(size_t)n * FIN + k] = __float2half_rn(W[k * FF + n]);
}

// ---------------------------------------------------------------------------
// Kernel 1: h = X @ W on HMMA, 2-product split (Xh*Wh + Xl*Wh).
// ---------------------------------------------------------------------------
__global__ __launch_bounds__(256, 1) void gemm_hmma(const float* __restrict__ X) {
    extern __shared__ char smem[];
    const uint32_t sb = smem_u32(smem);
    const int t = threadIdx.x;
    const int lane = t & 31, wid = t >> 5;
    const int midx = wid >> 2, nidx = wid & 3;
    const int i0 = blockIdx.x * 64;

    const int xr = t >> 2, xs = t & 3;
    const float* xptr = X + (size_t)(i0 + xr) * FIN + xs * 16;
    float4 xv[4];
#pragma unroll
    for (int q = 0; q < 4; q++) xv[q] = reinterpret_cast<const float4*>(xptr)[q];

    const __half* wh = g_wt_hi + (size_t)t * FIN;
    const uint32_t dBH = sb + GM_BH + (uint32_t)t * 144;
#pragma unroll
    for (int m = 0; m < 8; m++) CP16(dBH + m * 16, wh + m * 8);
    asm volatile("cp.async.commit_group;" ::: "memory");

    float acc[2][8][4];
#pragma unroll
    for (int a = 0; a < 2; a++)
#pragma unroll
        for (int b = 0; b < 8; b++)
#pragma unroll
            for (int c = 0; c < 4; c++) acc[a][b][c] = 0.f;

    const uint32_t arow = (uint32_t)(midx * 32 + ((lane >> 3) & 1) * 8 + (lane & 7));
    const uint32_t acolb = (uint32_t)((lane >> 4) * 16);
    const uint32_t brow0 = (uint32_t)(nidx * 64 + (lane >> 4) * 8 + (lane & 7));
    const uint32_t bcolb = (uint32_t)(((lane >> 3) & 1) * 16);

#pragma unroll 1
    for (int c = 0; c < 8; c++) {
        {
            const uint32_t aH = sb + GM_AH + (uint32_t)xr * 144 + (uint32_t)xs * 32;
            const uint32_t aL = sb + GM_AL + (uint32_t)xr * 144 + (uint32_t)xs * 32;
#pragma unroll
            for (int q = 0; q < 4; q++) {
                float4 v = xv[q];
                __half hx = __float2half_rn(v.x), hy = __float2half_rn(v.y);
                __half hz = __float2half_rn(v.z), hw = __float2half_rn(v.w);
                __half lx = __float2half_rn(v.x - __half2float(hx));
                __half ly = __float2half_rn(v.y - __half2float(hy));
                __half lz = __float2half_rn(v.z - __half2float(hz));
                __half lw = __float2half_rn(v.w - __half2float(hw));
                STSV2(aH + q * 8, h22u(__halves2half2(hx, hy)), h22u(__halves2half2(hz, hw)));
                STSV2(aL + q * 8, h22u(__halves2half2(lx, ly)), h22u(__halves2half2(lz, lw)));
            }
        }
        asm volatile("cp.async.wait_group 0;" ::: "memory");
        __syncthreads();
        if (c < 7) {
            const float* xp = xptr + (c + 1) * KC;
#pragma unroll
            for (int q = 0; q < 4; q++) xv[q] = reinterpret_cast<const float4*>(xp)[q];
        }
#pragma unroll
        for (int k16 = 0; k16 < 4; k16++) {
            uint32_t ah[2][4], al[2][4];
#pragma unroll
            for (int mt = 0; mt < 2; mt++) {
                LDSM4(ah[mt], sb + GM_AH + (arow + mt * 16) * 144 + k16 * 32 + acolb);
                LDSM4(al[mt], sb + GM_AL + (arow + mt * 16) * 144 + k16 * 32 + acolb);
            }
#pragma unroll
            for (int pr2 = 0; pr2 < 4; pr2++) {
                uint32_t bh[4];
                LDSM4(bh, sb + GM_BH + (brow0 + pr2 * 16) * 144 + k16 * 32 + bcolb);
#pragma unroll
                for (int mt = 0; mt < 2; mt++) {
                    MMA16816(acc[mt][2 * pr2], ah[mt], bh[0], bh[1]);
                    MMA16816(acc[mt][2 * pr2], al[mt], bh[0], bh[1]);
                    MMA16816(acc[mt][2 * pr2 + 1], ah[mt], bh[2], bh[3]);
                    MMA16816(acc[mt][2 * pr2 + 1], al[mt], bh[2], bh[3]);
                }
            }
        }
        __syncthreads();
        if (c < 7) {
#pragma unroll
            for (int m = 0; m < 8; m++) CP16(dBH + m * 16, wh + (c + 1) * KC + m * 8);
            asm volatile("cp.async.commit_group;" ::: "memory");
        }
    }

    // ---- epilogue: g_h fp32 + transpose to g_hT fp16 ----
#pragma unroll
    for (int mt = 0; mt < 2; mt++) {
        int lr0 = midx * 32 + mt * 16 + (lane >> 2);
        float* o0 = g_h + (size_t)(i0 + lr0) * FF;
#pragma unroll
        for (int nt = 0; nt < 8; nt++) {
            int col = nidx * 64 + nt * 8 + (lane & 3) * 2;
            *reinterpret_cast<float2*>(o0 + col) = make_float2(acc[mt][nt][0], acc[mt][nt][1]);
            *reinterpret_cast<float2*>(o0 + 8 * FF + col) = make_float2(acc[mt][nt][2], acc[mt][nt][3]);
            char* tb = smem + GM_BH + col * 144;
            *reinterpret_cast<__half*>(tb + lr0 * 2) = __float2half_rn(acc[mt][nt][0]);
            *reinterpret_cast<__half*>(tb + 144 + lr0 * 2) = __float2half_rn(acc[mt][nt][1]);
            *reinterpret_cast<__half*>(tb + (lr0 + 8) * 2) = __float2half_rn(acc[mt][nt][2]);
            *reinterpret_cast<__half*>(tb + 144 + (lr0 + 8) * 2) = __float2half_rn(acc[mt][nt][3]);
        }
    }
    __syncthreads();
    {
        uint4* dst = reinterpret_cast<uint4*>(g_hT + (size_t)t * NN + i0);
#pragma unroll
        for (int i = 0; i < 8; i++)
            dst[i] = *reinterpret_cast<const uint4*>(smem + GM_BH + t * 144 + i * 16);
    }
}

// ---------------------------------------------------------------------------
// Kernel 2: s1, s2 dot products (warp per row) + global max(s2) via atomicMax
// ---------------------------------------------------------------------------
__global__ __launch_bounds__(256) void svec_kernel(const float* __restrict__ a) {
    __shared__ float as[2 * FF];
    const int t = threadIdx.x;
    as[t] = a[t];
    as[t + 256] = a[t + 256];
    __syncthreads();
    const int warp = t >> 5, lane = t & 31;
    const int row = blockIdx.x * 8 + warp;
    float s1 = 0.f, s2 = 0.f;
#pragma unroll
    for (int q = 0; q < 8; q++) {
        int f = lane + 32 * q;
        float v = g_h[row * FF + f];
        s1 = fmaf(v, as[f], s1);
        s2 = fmaf(v, as[FF + f], s2);
    }
#pragma unroll
    for (int o = 16; o; o >>= 1) {
        s1 += __shfl_xor_sync(0xFFFFFFFFu, s1, o);
        s2 += __shfl_xor_sync(0xFFFFFFFFu, s2, o);
    }
    if (lane == 0) {
        g_s1[row] = s1;
        g_s2[row] = s2;
        atomicMax(&g_mxkey, f2key(s2));
    }
}

// ---------------------------------------------------------------------------
// P generator (16 j per thread, exp-free, inline adj mask, fp32 Z accum)
// ---------------------------------------------------------------------------
__device__ __forceinline__ void pgen(uint32_t sb, const char* smem, int bufp, int jc,
                                     const uint4& I0, const uint4& I1,
                                     const uint4& I2, const uint4& I3,
                                     __half2 A2, __half2 C2, int pr_, int seg,
                                     float& z) {
    const uint4* bd4s = reinterpret_cast<const uint4*>(smem + SM_BD) + (jc >> 2) + seg * 4;
    const uint32_t pst = sb + SM_P + (uint32_t)bufp * 9216 + (uint32_t)pr_ * 144 + (uint32_t)seg * 32;
    uint32_t m8[8];
    m8[0] = (uint32_t)I0.x * 0x3C00u + (uint32_t)I0.y * 0x3C000000u;
    m8[1] = (uint32_t)I0.z * 0x3C00u + (uint32_t)I0.w * 0x3C000000u;
    m8[2] = (uint32_t)I1.x * 0x3C00u + (uint32_t)I1.y * 0x3C000000u;
    m8[3] = (uint32_t)I1.z * 0x3C00u + (uint32_t)I1.w * 0x3C000000u;
    m8[4] = (uint32_t)I2.x * 0x3C00u + (uint32_t)I2.y * 0x3C000000u;
    m8[5] = (uint32_t)I2.z * 0x3C00u + (uint32_t)I2.w * 0x3C000000u;
    m8[6] = (uint32_t)I3.x * 0x3C00u + (uint32_t)I3.y * 0x3C000000u;
    m8[7] = (uint32_t)I3.z * 0x3C00u + (uint32_t)I3.w * 0x3C000000u;
#pragma unroll
    for (int q = 0; q < 4; q++) {
        uint4 bd = bd4s[q];
        __half2 m0 = __hmax2(__hmul2(A2, u2h2(bd.x)), __hmul2(C2, u2h2(bd.y)));
        __half2 m1 = __hmax2(__hmul2(A2, u2h2(bd.z)), __hmul2(C2, u2h2(bd.w)));
        __half2 r0 = __hmul2(m0, u2h2(m8[2 * q]));
        __half2 r1 = __hmul2(m1, u2h2(m8[2 * q + 1]));
        STSV2(pst + q * 8, h22u(r0), h22u(r1));
        float2 f0 = __half22float2(r0), f1 = __half22float2(r1);
        z += (f0.x + f0.y) + (f1.x + f1.y);
    }
}

// ---------------------------------------------------------------------------
// Kernel 4: fused GAT on HMMA. 128 CTAs x (M=64, N=256), K=8192 in 64-chunks.
// 256 threads, warp tile 32x64 (R11 shape). Software-pipelined fragments:
// bh double-buffered across pr2, af double-buffered across k16.
// ---------------------------------------------------------------------------
__global__ __launch_bounds__(256, 1) void gat_hmma(const int* __restrict__ adj,
                                                   float* __restrict__ out) {
    extern __shared__ char smem[];
    const uint32_t sb = smem_u32(smem);
    const int t = threadIdx.x;
    const int lane = t & 31, wid = t >> 5;
    const int midx = wid >> 2, nidx = wid & 3;
    const int i0 = blockIdx.x * MB;

    const int pr_ = t >> 2;
    const int seg = t & 3;
    const int* adjrow = adj + (size_t)(i0 + pr_) * NN + seg * 16;

    // B(0) cp.async early
    {
        const __half* sH = g_hT + (size_t)t * NN;
        const uint32_t dH = sb + SM_B + (uint32_t)t * 144;
#pragma unroll
        for (int i = 0; i < 8; i++) CP16(dH + i * 16, sH + i * 8);
        asm volatile("cp.async.commit_group;" ::: "memory");
    }
    uint4 I0 = reinterpret_cast<const uint4*>(adjrow)[0];
    uint4 I1 = reinterpret_cast<const uint4*>(adjrow)[1];
    uint4 I2 = reinterpret_cast<const uint4*>(adjrow)[2];
    uint4 I3 = reinterpret_cast<const uint4*>(adjrow)[3];

    // ---- build BD tables + AC in smem ----
    const float mx = key2f(g_mxkey);
    {
        const float2* s2p = reinterpret_cast<const float2*>(g_s2);
        uint2* bd = reinterpret_cast<uint2*>(smem + SM_BD);
        for (int j2 = t; j2 < NN / 2; j2 += 256) {
            float2 v = s2p[j2];
            float v0 = v.x - mx, v1 = v.y - mx;
            __half B0 = __float2half_rn(__expf(v0)), B1 = __float2half_rn(__expf(v1));
            __half D0 = __float2half_rn(__expf(0.2f * v0)), D1 = __float2half_rn(__expf(0.2f * v1));
            bd[j2] = make_uint2(h22u(__halves2half2(B0, B1)), h22u(__halves2half2(D0, D1)));
        }
        if (t < MB) {
            float u = g_s1[i0 + t] + mx;
            float mm = fmaxf(u, 0.2f * u);
            __half A = __float2half_rn(__expf(u - mm));
            __half C = __float2half_rn(__expf(0.2f * u - mm));
            reinterpret_cast<uint2*>(smem + SM_AC)[t] =
                make_uint2(h22u(__halves2half2(A, A)), h22u(__halves2half2(C, C)));
        }
    }
    __syncthreads();
    const uint2 ac = reinterpret_cast<const uint2*>(smem + SM_AC)[pr_];
    const __half2 A2 = u2h2(ac.x);
    const __half2 C2 = u2h2(ac.y);

    float z = 0.f;
    pgen(sb, smem, 0, 0, I0, I1, I2, I3, A2, C2, pr_, seg, z);
    {
        const uint4* na = reinterpret_cast<const uint4*>(adjrow + KC);
        I0 = na[0]; I1 = na[1]; I2 = na[2]; I3 = na[3];
    }

    float acc[2][8][4];
#pragma unroll
    for (int a = 0; a < 2; a++)
#pragma unroll
        for (int b = 0; b < 8; b++)
#pragma unroll
            for (int c = 0; c < 4; c++) acc[a][b][c] = 0.f;

    const uint32_t arow = (uint32_t)(midx * 32 + ((lane >> 3) & 1) * 8 + (lane & 7));
    const uint32_t acolb = (uint32_t)((lane >> 4) * 16);
    const uint32_t brow0 = (uint32_t)(nidx * 64 + (lane >> 4) * 8 + (lane & 7));
    const uint32_t bcolb = (uint32_t)(((lane >> 3) & 1) * 16);

#pragma unroll 1
    for (int c = 0; c < 128; c++) {
        const int buf = c & 1;
        const int jc = c * KC;

        asm volatile("cp.async.wait_group 0;" ::: "memory");  // B(c) landed
        __syncthreads();                                      // P(c) + B(c) visible

        if (c < 127) {  // stage B(c+1)
            const __half* sH = g_hT + (size_t)t * NN + jc + KC;
            const uint32_t dH = sb + SM_B + (uint32_t)(buf ^ 1) * 36864 + (uint32_t)t * 144;
#pragma unroll
            for (int i = 0; i < 8; i++) CP16(dH + i * 16, sH + i * 8);
            asm volatile("cp.async.commit_group;" ::: "memory");
        }

        const uint32_t Pb = sb + SM_P + (uint32_t)buf * 9216;
        const uint32_t Bb = sb + SM_B + (uint32_t)buf * 36864;

        // fragment pipeline warm-up
        uint32_t af[2][2][4], bh[2][4];
        LDSM4(af[0][0], Pb + arow * 144 + acolb);
        LDSM4(af[0][1], Pb + (arow + 16) * 144 + acolb);
        LDSM4(bh[0], Bb + brow0 * 144 + bcolb);

#pragma unroll
        for (int k16 = 0; k16 < 4; k16++) {
            const int ca = k16 & 1;
#pragma unroll
            for (int pr2 = 0; pr2 < 4; pr2++) {
                const int cb = (4 * k16 + pr2) & 1;
                // prefetch next bh (next pr2, or pr2=0 of next k16)
                if (!(k16 == 3 && pr2 == 3)) {
                    const int np = (pr2 + 1) & 3;
                    const int nk = k16 + (pr2 == 3 ? 1 : 0);
                    LDSM4(bh[cb ^ 1], Bb + (brow0 + np * 16) * 144 + nk * 32 + bcolb);
                }
                // prefetch af for next k16 early in this k16
                if (pr2 == 1 && k16 < 3) {
                    const uint32_t ko = (uint32_t)(k16 + 1) * 32;
                    LDSM4(af[ca ^ 1][0], Pb + arow * 144 + ko + acolb);
                    LDSM4(af[ca ^ 1][1], Pb + (arow + 16) * 144 + ko + acolb);
                }
                MMA16816(acc[0][2 * pr2], af[ca][0], bh[cb][0], bh[cb][1]);
                MMA16816(acc[0][2 * pr2 + 1], af[ca][0], bh[cb][2], bh[cb][3]);
                MMA16816(acc[1][2 * pr2], af[ca][1], bh[cb][0], bh[cb][1]);
                MMA16816(acc[1][2 * pr2 + 1], af[ca][1], bh[cb][2], bh[cb][3]);
            }
            if (k16 == 1) {  // P-gen(c+1) + adj prefetch under the MMAs
                if (c < 127)
                    pgen(sb, smem, buf ^ 1, jc + KC, I0, I1, I2, I3, A2, C2, pr_, seg, z);
                if (c < 126) {
                    const uint4* na = reinterpret_cast<const uint4*>(adjrow + jc + 2 * KC);
                    I0 = na[0]; I1 = na[1]; I2 = na[2]; I3 = na[3];
                }
            }
        }
    }
    __syncthreads();

    // ---- Z: reduce over the 4 seg-threads of each row ----
    z += __shfl_xor_sync(0xFFFFFFFFu, z, 1);
    z += __shfl_xor_sync(0xFFFFFFFFu, z, 2);
    float* zs = reinterpret_cast<float*>(smem + SM_ZS);
    if (seg == 0) zs[pr_] = z;
    __syncthreads();

    // ---- epilogue: 1/Z + ELU + store ----
#pragma unroll
    for (int mt = 0; mt < 2; mt++) {
        int lr0 = midx * 32 + mt * 16 + (lane >> 2);
        float inv0 = 1.0f / zs[lr0];
        float inv1 = 1.0f / zs[lr0 + 8];
        float* o0 = out + (size_t)(i0 + lr0) * FF;
#pragma unroll
        for (int nt = 0; nt < 8; nt++) {
            int col = nidx * 64 + nt * 8 + (lane & 3) * 2;
            float v0 = acc[mt][nt][0] * inv0, v1 = acc[mt][nt][1] * inv0;
            float v2 = acc[mt][nt][2] * inv1, v3 = acc[mt][nt][3] * inv1;
            v0 = v0 > 0.f ? v0 : (__expf(v0) - 1.f);
            v1 = v1 > 0.f ? v1 : (__expf(v1) - 1.f);
            v2 = v2 > 0.f ? v2 : (__expf(v2) - 1.f);
            v3 = v3 > 0.f ? v3 : (__expf(v3) - 1.f);
            *reinterpret_cast<float2*>(o0 + col) = make_float2(v0, v1);
            *reinterpret_cast<float2*>(o0 + 8 * FF + col) = make_float2(v2, v3);
        }
    }
}

// ---------------------------------------------------------------------------
extern "C" void kernel_launch(void* const* d_in, const int* in_sizes, int n_in,
                              void* d_out, int out_size) {
    const float* X = (const float*)d_in[0];   // [8192, 512]
    const int* adj = (const int*)d_in[1];     // [8192, 8192]
    const float* W = (const float*)d_in[2];   // [512, 256]
    const float* a = (const float*)d_in[3];   // [512, 1]
    float* out = (float*)d_out;               // [8192, 256]

    cudaFuncSetAttribute(gemm_hmma, cudaFuncAttributeMaxDynamicSharedMemorySize, GEMM_SMEM);
    cudaFuncSetAttribute(gat_hmma, cudaFuncAttributeMaxDynamicSharedMemorySize, GAT_SMEM);

    wconv<<<FF, FIN>>>(W);
    gemm_hmma<<<NN / 64, 256, GEMM_SMEM>>>(X);
    svec_kernel<<<NN / 8, 256>>>(a);
    gat_hmma<<<NN / MB, 256, GAT_SMEM>>>(adj, out);
}